// round 16
// baseline (speedup 1.0000x reference)
#include <cuda_runtime.h>
#include <cuda_fp16.h>
#include <math.h>

// PlanesweepCorrelation: N=2, C=64, S=32, H=128, W=160, G=8
#define NN 2
#define CC 64
#define SS 32
#define HH 128
#define WW 160
#define HWSZ (HH * WW)          // 20480
#define NPIX (NN * HWSZ)        // 40960
#define NG 8
#define CORR_ELEMS ((size_t)NN * NG * SS * HWSZ)   // 10,485,760
#define PIX_PER_BLK 32

// Dynamic smem layout (bytes):
//   s_t   : int4 [32][32]       = 16384   @ 0
//   s_c   : float[32][257]      = 32896   @ 16384
//   s_g   : float[64][33]       = 8448    @ 49280
//   s_m   : float[32][33]       = 4224    @ 57728
//   s_ref : float[32][68]       = 8704    @ 61952   (row stride 272B, 16B-aligned)
#define SMEM_T_OFF   0
#define SMEM_C_OFF   16384
#define SMEM_G_OFF   49280
#define SMEM_M_OFF   57728
#define SMEM_REF_OFF 61952
#define SMEM_TOTAL   70656

// Normalized NHWC src scratch (fp16). Ref is normalized in-block in corr.
__device__ __half g_srcT[NPIX * CC];

// ---------------------------------------------------------------------------
// Prepass (src only): L2-normalize over channels, transpose NCHW -> NHWC.
// ---------------------------------------------------------------------------
__global__ __launch_bounds__(256) void norm_transpose_kernel(
    const float* __restrict__ src)
{
    __half2* dst = (__half2*)g_srcT;

    __shared__ float tile[32][CC + 1];
    __shared__ float inv[32];

    int tid   = threadIdx.x;
    int pbase = blockIdx.x * 32;

    {
        int pp = tid & 31;
        int cc = tid >> 5;
        int p  = pbase + pp;
        int n  = p / HWSZ;
        int hw = p - n * HWSZ;
        const float* base = src + (size_t)n * CC * HWSZ + hw;
#pragma unroll
        for (int it = 0; it < 8; it++) {
            int c = cc + it * 8;
            tile[pp][c] = base[(size_t)c * HWSZ];
        }
    }
    __syncthreads();

    {
        int pp = tid >> 3;
        int k  = tid & 7;
        float s = 0.f;
#pragma unroll
        for (int j = 0; j < 8; j++) {
            float v = tile[pp][k * 8 + j];
            s += v * v;
        }
        s += __shfl_xor_sync(0xffffffffu, s, 1);
        s += __shfl_xor_sync(0xffffffffu, s, 2);
        s += __shfl_xor_sync(0xffffffffu, s, 4);
        if (k == 0) inv[pp] = 1.0f / (sqrtf(s) + 1e-9f);
    }
    __syncthreads();

#pragma unroll
    for (int it = 0; it < 4; it++) {
        int idx = it * 256 + tid;        // 0..1023
        int pp  = idx >> 5;              // pixel 0..31
        int c2  = idx & 31;              // half2 index 0..31
        float iv = inv[pp];
        float a = tile[pp][c2 * 2]     * iv;
        float b = tile[pp][c2 * 2 + 1] * iv;
        dst[(size_t)(pbase + pp) * 32 + c2] = __floats2half2_rn(a, b);
    }
}

__device__ __forceinline__ __half2 u2h2(unsigned u) {
    return *reinterpret_cast<const __half2*>(&u);
}

// ---------------------------------------------------------------------------
// Main kernel. 512 threads = 16 warps; block covers 32 consecutive pixels
// (each warp handles 2). Ref is loaded NCHW-coalesced and normalized
// in-block (fp32, smem); src gathered from fp16 NHWC scratch. Octet layout:
// lane = (oct = plane sub-index, gl = channel group). 4 planes per warp
// iteration; corner loads double-buffered. Store phase writes 128B runs.
// ---------------------------------------------------------------------------
__global__ void __launch_bounds__(512, 2) corr_kernel(
    const float* __restrict__ feat_ref,
    const float* __restrict__ grids, float* __restrict__ out)
{
    extern __shared__ char smem_raw[];
    int4  (*s_t)[SS]               = (int4 (*)[SS])(smem_raw + SMEM_T_OFF);
    float (*s_c)[SS * NG + 1]      = (float (*)[SS * NG + 1])(smem_raw + SMEM_C_OFF);
    float (*s_g)[PIX_PER_BLK + 1]  = (float (*)[PIX_PER_BLK + 1])(smem_raw + SMEM_G_OFF);
    float (*s_m)[SS + 1]           = (float (*)[SS + 1])(smem_raw + SMEM_M_OFF);
    float (*s_ref)[68]             = (float (*)[68])(smem_raw + SMEM_REF_OFF);

    const int t    = threadIdx.x;
    const int w    = t >> 5;         // 0..15
    const int lane = t & 31;
    const int oct  = lane >> 3;      // 0..3: plane sub-index
    const int gl   = lane & 7;       // 0..7: channel group

    const int blkpix = blockIdx.x * PIX_PER_BLK;
    const int n      = blkpix / HWSZ;      // HWSZ % 32 == 0: no straddle
    const int hw0    = blkpix - n * HWSZ;

    // ---- cooperative grid staging (coalesced) ----
    const float* gb_n = grids + (size_t)n * (2 * SS) * HWSZ;
#pragma unroll
    for (int it = 0; it < 4; it++) {
        int idx = it * 512 + t;          // 0..2047
        int sc  = idx >> 5;
        int pp  = idx & 31;
        s_g[sc][pp] = gb_n[(size_t)sc * HWSZ + hw0 + pp];
    }

    // ---- ref staging: NCHW coalesced load (one 128B row per warp-instr) ----
    {
        const float* rb = feat_ref + (size_t)n * CC * HWSZ + hw0;
#pragma unroll
        for (int it = 0; it < 4; it++) {
            int idx = it * 512 + t;      // 0..2047
            int c   = idx >> 5;          // channel 0..63
            int pp  = idx & 31;          // pixel
            s_ref[pp][c] = rb[(size_t)c * HWSZ + pp];
        }
    }
    __syncthreads();

    // ---- in-block ref normalization: 16 threads per pixel ----
    {
        int pp = t >> 4;                 // pixel 0..31
        int k  = t & 15;                 // 0..15, within half-warp
        float s = 0.f;
#pragma unroll
        for (int j = 0; j < 4; j++) {
            float v = s_ref[pp][k * 4 + j];
            s += v * v;
        }
        s += __shfl_xor_sync(0xffffffffu, s, 1);
        s += __shfl_xor_sync(0xffffffffu, s, 2);
        s += __shfl_xor_sync(0xffffffffu, s, 4);
        s += __shfl_xor_sync(0xffffffffu, s, 8);
        float iv = 1.0f / (sqrtf(s) + 1e-9f);
#pragma unroll
        for (int j = 0; j < 4; j++)
            s_ref[pp][k * 4 + j] *= iv;
    }
    __syncthreads();

    const char* sb = (const char*)(g_srcT + (size_t)n * HWSZ * CC) + gl * 16;

#pragma unroll
    for (int pi = 0; pi < 2; pi++) {
        const int p = w * 2 + pi;        // 0..31

        // ---- prologue: lane s computes plane-s table ----
        {
            const float gx = s_g[2 * lane][p];
            const float gy = s_g[2 * lane + 1][p];
            float ixf = gx - 0.5f, iyf = gy - 0.5f;
            float x0f = floorf(ixf), y0f = floorf(iyf);
            int   x0 = (int)x0f,   y0 = (int)y0f;
            float wx1 = ixf - x0f, wy1 = iyf - y0f;
            float wx0 = 1.f - wx1, wy0 = 1.f - wy1;
            bool vx0 = (x0 >= 0)  && (x0 <  WW);
            bool vx1 = (x0 >= -1) && (x0 <  WW - 1);
            bool vy0 = (y0 >= 0)  && (y0 <  HH);
            bool vy1 = (y0 >= -1) && (y0 <  HH - 1);
            float w00 = (vx0 && vy0) ? wx0 * wy0 : 0.f;
            float w10 = (vx1 && vy0) ? wx1 * wy0 : 0.f;
            float w01 = (vx0 && vy1) ? wx0 * wy1 : 0.f;
            float w11 = (vx1 && vy1) ? wx1 * wy1 : 0.f;
            float msum = w00 + w10 + w01 + w11;
            float mask = (msum < 0.9999f) ? 0.f : 1.f;
            int xc0 = min(max(x0, 0),     WW - 1);
            int xc1 = min(max(x0 + 1, 0), WW - 1);
            int yc0 = min(max(y0, 0),     HH - 1);
            int yc1 = min(max(y0 + 1, 0), HH - 1);
            int off = (yc0 * WW + xc0) * (CC * 2);   // bytes: fp16 row = 128B
            int dx  = (xc1 - xc0) * (CC * 2);        // 0 or 128
            int dy  = (yc1 - yc0) * (WW * CC * 2);   // 0 or 20480
            __half2 wlo = __floats2half2_rn(w00 * mask, w10 * mask);
            __half2 whi = __floats2half2_rn(w01 * mask, w11 * mask);
            int4 rec;
            rec.x = *reinterpret_cast<const int*>(&wlo);
            rec.y = *reinterpret_cast<const int*>(&whi);
            rec.z = off;
            rec.w = dx | (dy << 16);
            s_t[p][lane] = rec;
            s_m[p][lane] = mask;
        }
        __syncwarp();

        // ref channels for group gl: 8 fp32 from smem (broadcast LDS.128 x2)
        const float4* rp4 = (const float4*)&s_ref[p][gl * 8];
        const float4 ra = rp4[0];
        const float4 rb = rp4[1];
        const float2 r0 = make_float2(ra.x, ra.y);
        const float2 r1 = make_float2(ra.z, ra.w);
        const float2 r2 = make_float2(rb.x, rb.y);
        const float2 r3 = make_float2(rb.z, rb.w);

        float* scp = s_c[p];

        // ---- software-pipelined main loop: 4 planes/iter ----
        int4 rec = s_t[p][oct];
        {
            const int dx = rec.w & 0xffff;
            const int dy = rec.w >> 16;
            const char* a = sb + rec.z;
            uint4 c00 = *(const uint4*)(a);
            uint4 c10 = *(const uint4*)(a + dx);
            uint4 c01 = *(const uint4*)(a + dy);
            uint4 c11 = *(const uint4*)(a + dx + dy);

#pragma unroll
            for (int it = 0; it < 8; it++) {
                const int4 cur = rec;
                const uint4 b00 = c00, b10 = c10, b01 = c01, b11 = c11;

                if (it < 7) {                        // compile-time guard
                    rec = s_t[p][((it + 1) << 2) + oct];
                    const int ndx = rec.w & 0xffff;
                    const int ndy = rec.w >> 16;
                    const char* na = sb + rec.z;
                    c00 = *(const uint4*)(na);
                    c10 = *(const uint4*)(na + ndx);
                    c01 = *(const uint4*)(na + ndy);
                    c11 = *(const uint4*)(na + ndx + ndy);
                }

                const __half2 wp0 = u2h2((unsigned)cur.x);   // (w00, w10)
                const __half2 wp1 = u2h2((unsigned)cur.y);   // (w01, w11)
                const __half2 w00s = __low2half2(wp0);
                const __half2 w10s = __high2half2(wp0);
                const __half2 w01s = __low2half2(wp1);
                const __half2 w11s = __high2half2(wp1);

                // fp16 bilinear blend (mask folded into weights)
                __half2 a0 = __hmul2(w00s, u2h2(b00.x));
                __half2 a1 = __hmul2(w00s, u2h2(b00.y));
                __half2 a2 = __hmul2(w00s, u2h2(b00.z));
                __half2 a3 = __hmul2(w00s, u2h2(b00.w));
                a0 = __hfma2(w10s, u2h2(b10.x), a0);
                a1 = __hfma2(w10s, u2h2(b10.y), a1);
                a2 = __hfma2(w10s, u2h2(b10.z), a2);
                a3 = __hfma2(w10s, u2h2(b10.w), a3);
                a0 = __hfma2(w01s, u2h2(b01.x), a0);
                a1 = __hfma2(w01s, u2h2(b01.y), a1);
                a2 = __hfma2(w01s, u2h2(b01.z), a2);
                a3 = __hfma2(w01s, u2h2(b01.w), a3);
                a0 = __hfma2(w11s, u2h2(b11.x), a0);
                a1 = __hfma2(w11s, u2h2(b11.y), a1);
                a2 = __hfma2(w11s, u2h2(b11.z), a2);
                a3 = __hfma2(w11s, u2h2(b11.w), a3);

                // convert blended pairs, dot with fp32 ref
                float2 f0 = __half22float2(a0);
                float2 f1 = __half22float2(a1);
                float2 f2 = __half22float2(a2);
                float2 f3 = __half22float2(a3);
                float sum = f0.x * r0.x + f0.y * r0.y
                          + f1.x * r1.x + f1.y * r1.y
                          + f2.x * r2.x + f2.y * r2.y
                          + f3.x * r3.x + f3.y * r3.y;

                scp[(((it << 2) + oct) << 3) + gl] = sum;   // 128B run: 1 wf
            }
        }
        __syncwarp();
    }
    __syncthreads();

    // ---- store phase: 128B contiguous runs per warp-instr ----
    {
        const int pl = t & 31;           // pixel 0..31
        const int h  = t >> 5;           // 0..15
        float* po = out + (size_t)n * 256 * HWSZ + hw0 + pl;
#pragma unroll
        for (int i = 0; i < 16; i++) {
            int gs = i * 16 + h;         // gs = g*32 + s
            int s  = gs & 31;
            int g  = gs >> 5;
            po[(size_t)gs * HWSZ] = s_c[pl][s * 8 + g];
        }
        float* pm = out + CORR_ELEMS + (size_t)n * SS * HWSZ + hw0 + pl;
#pragma unroll
        for (int i = 0; i < 2; i++) {
            int s = i * 16 + h;
            pm[(size_t)s * HWSZ] = s_m[pl][s];
        }
    }
}

extern "C" void kernel_launch(void* const* d_in, const int* in_sizes, int n_in,
                              void* d_out, int out_size)
{
    const float* feat_ref = (const float*)d_in[0];
    const float* feat_src = (const float*)d_in[1];
    const float* grids    = (const float*)d_in[2];
    (void)in_sizes; (void)n_in; (void)out_size;

    // Raise dynamic-smem cap (host-side, immediate, idempotent).
    cudaFuncSetAttribute(corr_kernel,
                         cudaFuncAttributeMaxDynamicSharedMemorySize,
                         SMEM_TOTAL);

    // Prepass: src only (ref is normalized in-block inside corr_kernel).
    norm_transpose_kernel<<<NPIX / 32, 256>>>(feat_src);

    corr_kernel<<<NPIX / PIX_PER_BLK, 512, SMEM_TOTAL>>>(
        feat_ref, grids, (float*)d_out);
}